// round 13
// baseline (speedup 1.0000x reference)
#include <cuda_runtime.h>
#include <cuda_fp16.h>
#include <math.h>
#include <stdint.h>

#define BATCH   131072
#define HID     512
#define LDIM    8
#define NTH     45
#define NSTEPS  20

// ============================================================================
// Baseline-PTX tensor helpers (compute_103-safe: ldmatrix + mma.sync only)
// ============================================================================
__device__ __forceinline__ uint32_t smem_u32(const void* p) {
    uint32_t a;
    asm("{ .reg .u64 t; cvta.to.shared.u64 t, %1; cvt.u32.u64 %0, t; }"
        : "=r"(a) : "l"(p));
    return a;
}

#define LDSM4(r0, r1, r2, r3, addr) \
    asm volatile("ldmatrix.sync.aligned.m8n8.x4.shared.b16 {%0,%1,%2,%3}, [%4];" \
        : "=r"(r0), "=r"(r1), "=r"(r2), "=r"(r3) : "r"(addr))

// fp16 inputs, fp32 accumulate
#define MMA16816(d, a, b0, b1) \
    asm volatile("mma.sync.aligned.m16n8k16.row.col.f32.f16.f16.f32 " \
        "{%0,%1,%2,%3},{%4,%5,%6,%7},{%8,%9},{%0,%1,%2,%3};" \
        : "+f"((d)[0]), "+f"((d)[1]), "+f"((d)[2]), "+f"((d)[3]) \
        : "r"((a)[0]), "r"((a)[1]), "r"((a)[2]), "r"((a)[3]), \
          "r"(b0), "r"(b1))

__device__ __forceinline__ void cp16(uint32_t dst, const void* src) {
    asm volatile("cp.async.cg.shared.global [%0], [%1], 16;"
        :: "r"(dst), "l"(src));
}
#define CP_COMMIT() asm volatile("cp.async.commit_group;" ::: "memory")
#define CP_WAIT(n)  asm volatile("cp.async.wait_group %0;" :: "n"(n) : "memory")

__device__ __forceinline__ uint32_t pack_h2(float a, float b) {
    __half2 t = __floats2half2_rn(a, b);
    return reinterpret_cast<uint32_t&>(t);
}

// ============================================================================
// Scratch: activations single fp16 row-major. Weights single fp16,
// pre-transposed WT[n][kpad], zero-pad k>=K.
// ============================================================================
__device__ __half g_hA[BATCH * HID];
__device__ __half g_hB[BATCH * HID];
__device__ __half g_x[BATCH * 64];
__device__ float  g_z0[BATCH * LDIM];

__device__ __half g_w1[512 * 64];     // enc_W1  KPAD=64
__device__ __half g_w2[512 * 512];    // enc_W2  KPAD=512
__device__ __half g_d2[512 * 512];    // dec_W2  KPAD=512
__device__ __half g_d3[64 * 512];     // dec_W3  KPAD=512

// ============================================================================
// prep: weights in ONE launch (transpose + fp16 round + zero-pad)
// ============================================================================
#define SEG0 32768            // w1  (K=64,  N=512, KPAD=64)
#define SEG1 (SEG0 + 262144)  // w2  (K=512, N=512, KPAD=512)
#define SEG2 (SEG1 + 262144)  // d2  (K=512, N=512, KPAD=512)
#define SEG3 (SEG2 + 32768)   // d3  (K=512, N=64,  KPAD=512)

__global__ void prep_all_kernel(const float* __restrict__ eW1,
                                const float* __restrict__ eW2,
                                const float* __restrict__ dW2,
                                const float* __restrict__ dW3,
                                __half* __restrict__ w1, __half* __restrict__ w2,
                                __half* __restrict__ d2, __half* __restrict__ d3)
{
    int idx = blockIdx.x * 256 + threadIdx.x;
    if (idx >= SEG3) return;
    const float* W; __half* O; int K, N, KPAD, off;
    if (idx < SEG0)      { W = eW1; O = w1; K = 64;  N = 512; KPAD = 64;  off = 0;    }
    else if (idx < SEG1) { W = eW2; O = w2; K = 512; N = 512; KPAD = 512; off = SEG0; }
    else if (idx < SEG2) { W = dW2; O = d2; K = 512; N = 512; KPAD = 512; off = SEG1; }
    else                 { W = dW3; O = d3; K = 512; N = 64;  KPAD = 512; off = SEG2; }
    int i = idx - off;
    int n = i / KPAD, k = i % KPAD;
    float v = (k < K) ? W[(size_t)k * N + n] : 0.f;
    O[i] = __float2half_rn(v);
}

__global__ void prep_x_kernel(const float* __restrict__ x0,
                              __half* __restrict__ xo)
{
    size_t idx = (size_t)blockIdx.x * 256 + threadIdx.x;
    xo[idx] = __float2half_rn(x0[idx]);
}

// ============================================================================
// wide layer: O[B,512] = SiLU(LN(A[B,KPAD] @ W + b)), single fp16 operands,
// fp32 accumulate. CTA: M=64, N=512 (full row -> fused LN).
// 256 thr = 8 warps, warp tile m64 x n64 (warp w owns cols w*64..w*64+63).
// 255-reg budget (launch_bounds(256,1)) gives ptxas headroom to pipeline
// ldmatrix->mma chains (the 128-reg cap was the suspected serializer).
// BK=64, 2-stage cp.async double buffer. smem rows 144B -> conflict-free.
// WRITE_Z: skip activation store; fuse z0 = tanh(h @ W3 + b3).
// ============================================================================
#define LDR 144
#define WST      82944                          // bytes per stage
#define WS_A(s)  ((s) * WST)                    // A: 64*144  = 9216
#define WS_B(s)  ((s) * WST + 9216)             // B: 512*144 = 73728
#define WS_PAR   165888                         // bias/g/beta 3x2048
#define WS_RED   172032                         // sums/mu/rs 4x256
#define WS_Z     173056                         // 64x8 fp32 = 2048
#define WS_W3    175104                         // 512x8 fp32 = 16384
#define SM_WIDE  191488

template<int KPAD, bool WRITE_Z>
__global__ __launch_bounds__(256, 1)
void wide_mma_kernel(const __half* __restrict__ A,
                     const __half* __restrict__ W,
                     const float* __restrict__ bias,
                     const float* __restrict__ gamma,
                     const float* __restrict__ beta,
                     __half* __restrict__ O,
                     const float* __restrict__ W3,
                     const float* __restrict__ b3,
                     float* __restrict__ z0out)
{
    constexpr int NC = KPAD / 64;
    extern __shared__ char smem[];
    const uint32_t sb = smem_u32(smem);
    const int tid = threadIdx.x, lane = tid & 31, w = tid >> 5;  // 8 warps
    const int nbase = w * 64;
    const int tile = blockIdx.x;                      // 64-row tile

    float* sBias = (float*)(smem + WS_PAR);
    float* sG    = (float*)(smem + WS_PAR + 2048);
    float* sBe   = (float*)(smem + WS_PAR + 4096);
    float* sSum  = (float*)(smem + WS_RED);
    float* sSum2 = (float*)(smem + WS_RED + 256);
    float* sMu   = (float*)(smem + WS_RED + 512);
    float* sRs   = (float*)(smem + WS_RED + 768);
    float* sZ    = (float*)(smem + WS_Z);
    float* sW3   = (float*)(smem + WS_W3);

    for (int i = tid; i < 512; i += 256) {
        sBias[i] = bias[i]; sG[i] = gamma[i]; sBe[i] = beta[i];
    }
    if (tid < 64) { sSum[tid] = 0.f; sSum2[tid] = 0.f; }
    if (WRITE_Z) {
        for (int i = tid; i < 512; i += 256) sZ[i] = 0.f;
        for (int i = tid; i < 512 * 8; i += 256) sW3[i] = W3[i];
    }

    // chunk loader: B (512 rows x 128B), A (64 rows x 128B)
    auto load_chunk = [&](int c, int sel) {
        const int kbase = c * 64;
        const uint32_t bB = sb + WS_B(sel);
#pragma unroll
        for (int i = tid; i < 4096; i += 256) {
            const int row = i >> 3, j = i & 7;
            cp16(bB + row * LDR + j * 16,
                 (const char*)W + ((size_t)row * KPAD + kbase) * 2 + j * 16);
        }
#pragma unroll
        for (int i = tid; i < 512; i += 256) {        // 64 rows x 8 quads
            const int row = i >> 3, j = i & 7;
            cp16(sb + WS_A(sel) + row * LDR + j * 16,
                 (const char*)A + (((size_t)tile * 64 + row) * KPAD + kbase) * 2 + j * 16);
        }
        CP_COMMIT();
    };

    load_chunk(0, 0);
    if (NC > 1) load_chunk(1, 1); else CP_COMMIT();

    float acc[4][8][4];                               // m64 x n64 warp tile
#pragma unroll
    for (int i = 0; i < 4; i++)
#pragma unroll
        for (int j = 0; j < 8; j++)
#pragma unroll
            for (int r = 0; r < 4; r++) acc[i][j][r] = 0.f;

    const int arow = ((lane >> 3) & 1) * 8 + (lane & 7);
    const int acol = (lane >> 4) * 8;
    const int brow = ((lane >> 4) & 1) * 8 + (lane & 7);
    const int bcol = ((lane >> 3) & 1) * 8;

#pragma unroll 1
    for (int c = 0; c < NC; c++) {
        if (c + 1 < NC) CP_WAIT(1); else CP_WAIT(0);
        __syncthreads();
        const int sel = c & 1;
        const uint32_t bA = sb + WS_A(sel);
        const uint32_t bB = sb + WS_B(sel);
#pragma unroll
        for (int ks = 0; ks < 64; ks += 16) {
            uint32_t ah[4][4];
#pragma unroll
            for (int mf = 0; mf < 4; mf++) {
                const uint32_t ao = (uint32_t)((mf * 16 + arow) * LDR + (ks + acol) * 2);
                LDSM4(ah[mf][0], ah[mf][1], ah[mf][2], ah[mf][3], bA + ao);
            }
#pragma unroll
            for (int nq = 0; nq < 4; nq++) {
                const uint32_t bo = (uint32_t)((nbase + nq * 16 + brow) * LDR
                                               + (ks + bcol) * 2);
                uint32_t b[4];
                LDSM4(b[0], b[1], b[2], b[3], bB + bo);
#pragma unroll
                for (int mf = 0; mf < 4; mf++) {
                    MMA16816(acc[mf][nq * 2],     ah[mf], b[0], b[1]);
                    MMA16816(acc[mf][nq * 2 + 1], ah[mf], b[2], b[3]);
                }
            }
        }
        __syncthreads();
        if (c + 2 < NC) load_chunk(c + 2, sel);
    }

    // ---------------- epilogue: bias -> LN stats ----------------------------
#pragma unroll
    for (int mf = 0; mf < 4; mf++)
#pragma unroll
        for (int rh = 0; rh < 2; rh++) {
            float s = 0.f, s2 = 0.f;
#pragma unroll
            for (int idx = 0; idx < 8; idx++) {
                const int c0 = nbase + idx * 8 + (lane & 3) * 2;
                float v0 = acc[mf][idx][rh * 2]     + sBias[c0];
                float v1 = acc[mf][idx][rh * 2 + 1] + sBias[c0 + 1];
                acc[mf][idx][rh * 2] = v0; acc[mf][idx][rh * 2 + 1] = v1;
                s += v0 + v1; s2 += v0 * v0 + v1 * v1;
            }
            s  += __shfl_xor_sync(0xffffffffu, s, 1);
            s  += __shfl_xor_sync(0xffffffffu, s, 2);
            s2 += __shfl_xor_sync(0xffffffffu, s2, 1);
            s2 += __shfl_xor_sync(0xffffffffu, s2, 2);
            if ((lane & 3) == 0) {
                const int row = mf * 16 + (lane >> 2) + rh * 8;
                atomicAdd(&sSum[row], s);
                atomicAdd(&sSum2[row], s2);
            }
        }
    __syncthreads();
    if (tid < 64) {
        const float mu = sSum[tid] * (1.f / 512.f);
        const float var = sSum2[tid] * (1.f / 512.f) - mu * mu;
        sMu[tid] = mu; sRs[tid] = rsqrtf(var + 1e-5f);
    }
    __syncthreads();

    // ---------------- LN + SiLU, store fp16 or fused z = tanh(h@W3+b3) ------
#pragma unroll
    for (int mf = 0; mf < 4; mf++)
#pragma unroll
        for (int rh = 0; rh < 2; rh++) {
            const int row = mf * 16 + (lane >> 2) + rh * 8;
            const float mu = sMu[row], rs = sRs[row];
            float zp[8];
            if (WRITE_Z) {
#pragma unroll
                for (int j = 0; j < 8; j++) zp[j] = 0.f;
            }
            const size_t rowg = (size_t)tile * 64 + row;
#pragma unroll
            for (int idx = 0; idx < 8; idx++) {
                const int c0 = nbase + idx * 8 + (lane & 3) * 2;
                float y0 = (acc[mf][idx][rh * 2]     - mu) * rs * sG[c0]     + sBe[c0];
                float y1 = (acc[mf][idx][rh * 2 + 1] - mu) * rs * sG[c0 + 1] + sBe[c0 + 1];
                y0 = y0 * (1.f / (1.f + __expf(-y0)));
                y1 = y1 * (1.f / (1.f + __expf(-y1)));
                if (WRITE_Z) {
                    const float* w0 = sW3 + c0 * 8;
#pragma unroll
                    for (int j = 0; j < 8; j++) {
                        zp[j] = fmaf(y0, w0[j], zp[j]);
                        zp[j] = fmaf(y1, w0[8 + j], zp[j]);
                    }
                } else {
                    *(uint32_t*)(O + rowg * 512 + c0) = pack_h2(y0, y1);
                }
            }
            if (WRITE_Z) {
#pragma unroll
                for (int j = 0; j < 8; j++) {
                    zp[j] += __shfl_xor_sync(0xffffffffu, zp[j], 1);
                    zp[j] += __shfl_xor_sync(0xffffffffu, zp[j], 2);
                }
                if ((lane & 3) == 0)
#pragma unroll
                    for (int j = 0; j < 8; j++)
                        atomicAdd(&sZ[row * 8 + j], zp[j]);
            }
        }

    if (WRITE_Z) {
        __syncthreads();
        if (tid < 64) {
            const size_t rowg = (size_t)tile * 64 + tid;
#pragma unroll
            for (int j = 0; j < 8; j++)
                z0out[rowg * 8 + j] = tanhf(sZ[tid * 8 + j] + __ldg(b3 + j));
        }
    }
}

// ============================================================================
// out layer: out[B,64] = A[B,512] @ W3 + b3 (fp32 out, no LN).
// CTA: M=128, N=64. 256 thr = 8 warps (4Mx2N), warp m32 x n32. BK=64,
// 2-stage, 2 CTAs/SM. (Unchanged from round 12.)
// ============================================================================
#define OST      27648
#define OS_A(s)  ((s) * OST)                    // 128*144 = 18432
#define OS_B(s)  ((s) * OST + 18432)            // 64*144  = 9216
#define SM_OUT   55296

__global__ __launch_bounds__(256, 2)
void out_mma_kernel(const __half* __restrict__ A,
                    const __half* __restrict__ W,
                    const float* __restrict__ bias,
                    float* __restrict__ out)
{
    constexpr int NC = 8;
    extern __shared__ char smem[];
    const uint32_t sb = smem_u32(smem);
    const int tid = threadIdx.x, lane = tid & 31, w = tid >> 5;
    const int warpM = w >> 1, warpN = w & 1;
    const int nbase = warpN * 32;
    const int tile = blockIdx.x;

    auto load_chunk = [&](int c, int sel) {
        const int kbase = c * 64;
#pragma unroll
        for (int i = tid; i < 512; i += 256) {       // 64 rows x 8 quads
            const int row = i >> 3, j = i & 7;
            cp16(sb + OS_B(sel) + row * LDR + j * 16,
                 (const char*)W + ((size_t)row * 512 + kbase) * 2 + j * 16);
        }
#pragma unroll
        for (int i = tid; i < 1024; i += 256) {      // 128 rows x 8 quads
            const int row = i >> 3, j = i & 7;
            cp16(sb + OS_A(sel) + row * LDR + j * 16,
                 (const char*)A + (((size_t)tile * 128 + row) * 512 + kbase) * 2 + j * 16);
        }
        CP_COMMIT();
    };

    load_chunk(0, 0);
    load_chunk(1, 1);

    float acc[2][4][4];
#pragma unroll
    for (int i = 0; i < 2; i++)
#pragma unroll
        for (int j = 0; j < 4; j++)
#pragma unroll
            for (int r = 0; r < 4; r++) acc[i][j][r] = 0.f;

    const int arow = ((lane >> 3) & 1) * 8 + (lane & 7);
    const int acol = (lane >> 4) * 8;
    const int brow = ((lane >> 4) & 1) * 8 + (lane & 7);
    const int bcol = ((lane >> 3) & 1) * 8;

#pragma unroll 1
    for (int c = 0; c < NC; c++) {
        if (c + 1 < NC) CP_WAIT(1); else CP_WAIT(0);
        __syncthreads();
        const int sel = c & 1;
        const uint32_t bA = sb + OS_A(sel);
        const uint32_t bB = sb + OS_B(sel);
#pragma unroll
        for (int ks = 0; ks < 64; ks += 16) {
            uint32_t ah[2][4];
#pragma unroll
            for (int mf = 0; mf < 2; mf++) {
                const uint32_t ao = (uint32_t)((warpM * 32 + mf * 16 + arow) * LDR
                                               + (ks + acol) * 2);
                LDSM4(ah[mf][0], ah[mf][1], ah[mf][2], ah[mf][3], bA + ao);
            }
#pragma unroll
            for (int nq = 0; nq < 2; nq++) {
                const uint32_t bo = (uint32_t)((nbase + nq * 16 + brow) * LDR
                                               + (ks + bcol) * 2);
                uint32_t b[4];
                LDSM4(b[0], b[1], b[2], b[3], bB + bo);
#pragma unroll
                for (int mf = 0; mf < 2; mf++) {
                    MMA16816(acc[mf][nq * 2],     ah[mf], b[0], b[1]);
                    MMA16816(acc[mf][nq * 2 + 1], ah[mf], b[2], b[3]);
                }
            }
        }
        __syncthreads();
        if (c + 2 < NC) load_chunk(c + 2, sel);
    }

#pragma unroll
    for (int mf = 0; mf < 2; mf++)
#pragma unroll
        for (int rh = 0; rh < 2; rh++) {
            const int row = warpM * 32 + mf * 16 + (lane >> 2) + rh * 8;
            const size_t rowg = (size_t)tile * 128 + row;
#pragma unroll
            for (int idx = 0; idx < 4; idx++) {
                const int c0 = nbase + idx * 8 + (lane & 3) * 2;
                float2 o;
                o.x = acc[mf][idx][rh * 2]     + __ldg(bias + c0);
                o.y = acc[mf][idx][rh * 2 + 1] + __ldg(bias + c0 + 1);
                *(float2*)(out + rowg * 64 + c0) = o;
            }
        }
}

// ============================================================================
// integrator + FUSED dec layer 1: per-thread 20 Euler steps -> z[8], then
// warp-per-row matvec h = SiLU(LN(z @ dW1 + b1)) with dW1 fp32 in smem
// (K=8 -> FFMA beats MMA; removes a full wide<64> launch + zt round-trip).
// ============================================================================
__global__ __launch_bounds__(256, 4)
void integrate_dec1_kernel(const float* __restrict__ z0,
                           const float* __restrict__ dtv,
                           const float* __restrict__ Xi,
                           const float* __restrict__ W1,   // dec_W1 [8][512] fp32
                           const float* __restrict__ b1,
                           const float* __restrict__ g1,
                           const float* __restrict__ be1,
                           __half* __restrict__ O)
{
    __shared__ float Xis[NTH * LDIM];
    __shared__ float sW[8 * 512];
    __shared__ float sB1[512], sG1[512], sBe1[512];
    __shared__ float sZr[256 * 9];                 // padded row stride 9

    const int tid = threadIdx.x, lane = tid & 31, w = tid >> 5;
    for (int i = tid; i < NTH * LDIM; i += 256) Xis[i] = Xi[i];
    for (int i = tid; i < 8 * 512; i += 256) sW[i] = W1[i];
    for (int i = tid; i < 512; i += 256) { sB1[i] = b1[i]; sG1[i] = g1[i]; sBe1[i] = be1[i]; }
    __syncthreads();

    // ---- phase 1: per-thread latent integration ----
    const size_t row = (size_t)blockIdx.x * 256 + tid;
    float z[8];
    *(float4*)&z[0] = *(const float4*)(z0 + row * 8);
    *(float4*)&z[4] = *(const float4*)(z0 + row * 8 + 4);
    const float dt = dtv[row] * (1.f / (float)NSTEPS);

#pragma unroll 1
    for (int s = 0; s < NSTEPS; s++) {
        float zd[8];
#pragma unroll
        for (int j = 0; j < 8; j++) zd[j] = Xis[j];
#pragma unroll
        for (int i = 0; i < 8; i++) {
            const float t = z[i];
#pragma unroll
            for (int j = 0; j < 8; j++)
                zd[j] = fmaf(t, Xis[(1 + i) * 8 + j], zd[j]);
        }
        int idx = 9;
#pragma unroll
        for (int i = 0; i < 8; i++)
#pragma unroll
            for (int k = i; k < 8; k++) {
                const float q = z[i] * z[k];
#pragma unroll
                for (int j = 0; j < 8; j++)
                    zd[j] = fmaf(q, Xis[idx * 8 + j], zd[j]);
                idx++;
            }
#pragma unroll
        for (int j = 0; j < 8; j++) z[j] = fmaf(zd[j], dt, z[j]);
    }
#pragma unroll
    for (int j = 0; j < 8; j++) sZr[tid * 9 + j] = z[j];
    __syncthreads();

    // ---- phase 2: warp-per-row dec1 matvec + LN + SiLU ----
    const size_t rowbase = (size_t)blockIdx.x * 256;
#pragma unroll 1
    for (int it = 0; it < 32; it++) {
        const int lr = it * 8 + w;                 // local row 0..255
        float zz[8];
#pragma unroll
        for (int k = 0; k < 8; k++) zz[k] = sZr[lr * 9 + k];   // broadcast
        float acc[16];
#pragma unroll
        for (int j = 0; j < 16; j++) {
            const int c = j * 32 + lane;
            float a = sB1[c];
#pragma unroll
            for (int k = 0; k < 8; k++) a = fmaf(zz[k], sW[k * 512 + c], a);
            acc[j] = a;
        }
        float s = 0.f, s2 = 0.f;
#pragma unroll
        for (int j = 0; j < 16; j++) { s += acc[j]; s2 += acc[j] * acc[j]; }
#pragma unroll
        for (int o = 16; o; o >>= 1) {
            s  += __shfl_xor_sync(0xffffffffu, s, o);
            s2 += __shfl_xor_sync(0xffffffffu, s2, o);
        }
        const float mu = s * (1.f / 512.f);
        const float rs = rsqrtf(s2 * (1.f / 512.f) - mu * mu + 1e-5f);
        __half* orow = O + (rowbase + lr) * 512;
#pragma unroll
        for (int j = 0; j < 16; j++) {
            const int c = j * 32 + lane;
            float y = (acc[j] - mu) * rs * sG1[c] + sBe1[c];
            y = y * (1.f / (1.f + __expf(-y)));
            orow[c] = __float2half_rn(y);
        }
    }
}

// ============================================================================
extern "C" void kernel_launch(void* const* d_in, const int* in_sizes, int n_in,
                              void* d_out, int out_size)
{
    (void)in_sizes; (void)n_in; (void)out_size;
    const float* x0   = (const float*)d_in[0];
    const float* dtn  = (const float*)d_in[1];
    const float* eW1  = (const float*)d_in[4];
    const float* eb1  = (const float*)d_in[5];
    const float* eg1  = (const float*)d_in[6];
    const float* ebe1 = (const float*)d_in[7];
    const float* eW2  = (const float*)d_in[8];
    const float* eb2  = (const float*)d_in[9];
    const float* eg2  = (const float*)d_in[10];
    const float* ebe2 = (const float*)d_in[11];
    const float* eW3  = (const float*)d_in[12];
    const float* eb3  = (const float*)d_in[13];
    const float* dW1  = (const float*)d_in[14];
    const float* db1  = (const float*)d_in[15];
    const float* dg1  = (const float*)d_in[16];
    const float* dbe1 = (const float*)d_in[17];
    const float* dW2  = (const float*)d_in[18];
    const float* db2  = (const float*)d_in[19];
    const float* dg2  = (const float*)d_in[20];
    const float* dbe2 = (const float*)d_in[21];
    const float* dW3  = (const float*)d_in[22];
    const float* db3  = (const float*)d_in[23];
    const float* Xi   = (const float*)d_in[24];
    float* out = (float*)d_out;

    __half *hA, *hB, *xh;
    __half *w1, *w2, *d2, *d3;
    float* z0;
    cudaGetSymbolAddress((void**)&hA, g_hA);
    cudaGetSymbolAddress((void**)&hB, g_hB);
    cudaGetSymbolAddress((void**)&xh, g_x);
    cudaGetSymbolAddress((void**)&z0, g_z0);
    cudaGetSymbolAddress((void**)&w1, g_w1);
    cudaGetSymbolAddress((void**)&w2, g_w2);
    cudaGetSymbolAddress((void**)&d2, g_d2);
    cudaGetSymbolAddress((void**)&d3, g_d3);

    cudaFuncSetAttribute(wide_mma_kernel<64, false>,
        cudaFuncAttributeMaxDynamicSharedMemorySize, SM_WIDE);
    cudaFuncSetAttribute(wide_mma_kernel<512, false>,
        cudaFuncAttributeMaxDynamicSharedMemorySize, SM_WIDE);
    cudaFuncSetAttribute(wide_mma_kernel<512, true>,
        cudaFuncAttributeMaxDynamicSharedMemorySize, SM_WIDE);
    cudaFuncSetAttribute(out_mma_kernel,
        cudaFuncAttributeMaxDynamicSharedMemorySize, SM_OUT);

    // ---- prep ----
    prep_all_kernel<<<(SEG3 + 255) / 256, 256>>>(eW1, eW2, dW2, dW3,
                                                 w1, w2, d2, d3);
    prep_x_kernel<<<(BATCH * 64) / 256, 256>>>(x0, xh);

    const int nwide = BATCH / 64;    // 2048

    // ---- pipeline ----
    // encoder layer 1
    wide_mma_kernel<64, false><<<nwide, 256, SM_WIDE>>>(
        xh, w1, eb1, eg1, ebe1, hA, nullptr, nullptr, nullptr);
    // encoder layer 2 + fused layer 3 -> z0
    wide_mma_kernel<512, true><<<nwide, 256, SM_WIDE>>>(
        hA, w2, eb2, eg2, ebe2, nullptr, eW3, eb3, z0);
    // integrator + fused decoder layer 1 -> hA
    integrate_dec1_kernel<<<BATCH / 256, 256>>>(z0, dtn, Xi, dW1, db1, dg1, dbe1, hA);
    // decoder layer 2
    wide_mma_kernel<512, false><<<nwide, 256, SM_WIDE>>>(
        hA, d2, db2, dg2, dbe2, hB, nullptr, nullptr, nullptr);
    // decoder output layer
    out_mma_kernel<<<BATCH / 128, 256, SM_OUT>>>(hB, d3, db3, out);
}

// round 14
// speedup vs baseline: 1.3020x; 1.3020x over previous
#include <cuda_runtime.h>
#include <cuda_fp16.h>
#include <math.h>
#include <stdint.h>

#define BATCH   131072
#define HID     512
#define LDIM    8
#define NTH     45
#define NSTEPS  20

// ============================================================================
// Baseline-PTX tensor helpers (compute_103-safe: ldmatrix + mma.sync only)
// ============================================================================
__device__ __forceinline__ uint32_t smem_u32(const void* p) {
    uint32_t a;
    asm("{ .reg .u64 t; cvta.to.shared.u64 t, %1; cvt.u32.u64 %0, t; }"
        : "=r"(a) : "l"(p));
    return a;
}

#define LDSM4(r0, r1, r2, r3, addr) \
    asm volatile("ldmatrix.sync.aligned.m8n8.x4.shared.b16 {%0,%1,%2,%3}, [%4];" \
        : "=r"(r0), "=r"(r1), "=r"(r2), "=r"(r3) : "r"(addr))

// fp16 inputs, fp32 accumulate
#define MMA16816(d, a, b0, b1) \
    asm volatile("mma.sync.aligned.m16n8k16.row.col.f32.f16.f16.f32 " \
        "{%0,%1,%2,%3},{%4,%5,%6,%7},{%8,%9},{%0,%1,%2,%3};" \
        : "+f"((d)[0]), "+f"((d)[1]), "+f"((d)[2]), "+f"((d)[3]) \
        : "r"((a)[0]), "r"((a)[1]), "r"((a)[2]), "r"((a)[3]), \
          "r"(b0), "r"(b1))

__device__ __forceinline__ void cp16(uint32_t dst, const void* src) {
    asm volatile("cp.async.cg.shared.global [%0], [%1], 16;"
        :: "r"(dst), "l"(src));
}
#define CP_COMMIT() asm volatile("cp.async.commit_group;" ::: "memory")
#define CP_WAIT(n)  asm volatile("cp.async.wait_group %0;" :: "n"(n) : "memory")

__device__ __forceinline__ uint32_t pack_h2(float a, float b) {
    __half2 t = __floats2half2_rn(a, b);
    return reinterpret_cast<uint32_t&>(t);
}

// ============================================================================
// Scratch: activations single fp16 row-major. Weights single fp16,
// pre-transposed WT[n][kpad], zero-pad k>=K.
// ============================================================================
__device__ __half g_hA[BATCH * HID];
__device__ __half g_hB[BATCH * HID];
__device__ __half g_x[BATCH * 64];
__device__ float  g_z0[BATCH * LDIM];

__device__ __half g_w1[512 * 64];     // enc_W1  KPAD=64
__device__ __half g_w2[512 * 512];    // enc_W2  KPAD=512
__device__ __half g_d2[512 * 512];    // dec_W2  KPAD=512
__device__ __half g_d3[64 * 512];     // dec_W3  KPAD=512

// ============================================================================
// prep: weights in ONE launch (transpose + fp16 round + zero-pad)
// ============================================================================
#define SEG0 32768            // w1  (K=64,  N=512, KPAD=64)
#define SEG1 (SEG0 + 262144)  // w2  (K=512, N=512, KPAD=512)
#define SEG2 (SEG1 + 262144)  // d2  (K=512, N=512, KPAD=512)
#define SEG3 (SEG2 + 32768)   // d3  (K=512, N=64,  KPAD=512)

__global__ void prep_all_kernel(const float* __restrict__ eW1,
                                const float* __restrict__ eW2,
                                const float* __restrict__ dW2,
                                const float* __restrict__ dW3,
                                __half* __restrict__ w1, __half* __restrict__ w2,
                                __half* __restrict__ d2, __half* __restrict__ d3)
{
    int idx = blockIdx.x * 256 + threadIdx.x;
    if (idx >= SEG3) return;
    const float* W; __half* O; int K, N, KPAD, off;
    if (idx < SEG0)      { W = eW1; O = w1; K = 64;  N = 512; KPAD = 64;  off = 0;    }
    else if (idx < SEG1) { W = eW2; O = w2; K = 512; N = 512; KPAD = 512; off = SEG0; }
    else if (idx < SEG2) { W = dW2; O = d2; K = 512; N = 512; KPAD = 512; off = SEG1; }
    else                 { W = dW3; O = d3; K = 512; N = 64;  KPAD = 512; off = SEG2; }
    int i = idx - off;
    int n = i / KPAD, k = i % KPAD;
    float v = (k < K) ? W[(size_t)k * N + n] : 0.f;
    O[i] = __float2half_rn(v);
}

__global__ void prep_x_kernel(const float* __restrict__ x0,
                              __half* __restrict__ xo)
{
    size_t idx = (size_t)blockIdx.x * 256 + threadIdx.x;
    xo[idx] = __float2half_rn(x0[idx]);
}

// ============================================================================
// Shared smem layout for wide kernels
// ============================================================================
#define LDR 144
#define WST      82944                          // bytes per stage
#define WS_A(s)  ((s) * WST)                    // A: 64*144  = 9216
#define WS_B(s)  ((s) * WST + 9216)             // B: 512*144 = 73728
#define WS_PAR   165888                         // bias/g/beta 3x2048
#define WS_RED   172032                         // sums/mu/rs 4x256
#define WS_Z     173056                         // 64x8 fp32 = 2048
#define WS_W3    175104                         // 512x8 fp32 = 16384
#define SM_WIDE  191488

// ============================================================================
// wide_mma_k512: O[B,512] = SiLU(LN(A[B,512] @ W + b)). 256 thr = 8 warps,
// warp tile m64 x n64, 255-reg budget (the round-13 winner: 522us/layer).
// BK=64, 2-stage cp.async. WRITE_Z: fuse z0 = tanh(h @ W3 + b3).
// ============================================================================
template<bool WRITE_Z>
__global__ __launch_bounds__(256, 1)
void wide_mma_k512(const __half* __restrict__ A,
                   const __half* __restrict__ W,
                   const float* __restrict__ bias,
                   const float* __restrict__ gamma,
                   const float* __restrict__ beta,
                   __half* __restrict__ O,
                   const float* __restrict__ W3,
                   const float* __restrict__ b3,
                   float* __restrict__ z0out)
{
    constexpr int NC = 8;
    extern __shared__ char smem[];
    const uint32_t sb = smem_u32(smem);
    const int tid = threadIdx.x, lane = tid & 31, w = tid >> 5;  // 8 warps
    const int nbase = w * 64;
    const int tile = blockIdx.x;                      // 64-row tile

    float* sBias = (float*)(smem + WS_PAR);
    float* sG    = (float*)(smem + WS_PAR + 2048);
    float* sBe   = (float*)(smem + WS_PAR + 4096);
    float* sSum  = (float*)(smem + WS_RED);
    float* sSum2 = (float*)(smem + WS_RED + 256);
    float* sMu   = (float*)(smem + WS_RED + 512);
    float* sRs   = (float*)(smem + WS_RED + 768);
    float* sZ    = (float*)(smem + WS_Z);
    float* sW3   = (float*)(smem + WS_W3);

    for (int i = tid; i < 512; i += 256) {
        sBias[i] = bias[i]; sG[i] = gamma[i]; sBe[i] = beta[i];
    }
    if (tid < 64) { sSum[tid] = 0.f; sSum2[tid] = 0.f; }
    if (WRITE_Z) {
        for (int i = tid; i < 512; i += 256) sZ[i] = 0.f;
        for (int i = tid; i < 512 * 8; i += 256) sW3[i] = W3[i];
    }

    auto load_chunk = [&](int c, int sel) {
        const int kbase = c * 64;
        const uint32_t bB = sb + WS_B(sel);
#pragma unroll
        for (int i = tid; i < 4096; i += 256) {
            const int row = i >> 3, j = i & 7;
            cp16(bB + row * LDR + j * 16,
                 (const char*)W + ((size_t)row * 512 + kbase) * 2 + j * 16);
        }
#pragma unroll
        for (int i = tid; i < 512; i += 256) {        // 64 rows x 8 quads
            const int row = i >> 3, j = i & 7;
            cp16(sb + WS_A(sel) + row * LDR + j * 16,
                 (const char*)A + (((size_t)tile * 64 + row) * 512 + kbase) * 2 + j * 16);
        }
        CP_COMMIT();
    };

    load_chunk(0, 0);
    load_chunk(1, 1);

    float acc[4][8][4];                               // m64 x n64 warp tile
#pragma unroll
    for (int i = 0; i < 4; i++)
#pragma unroll
        for (int j = 0; j < 8; j++)
#pragma unroll
            for (int r = 0; r < 4; r++) acc[i][j][r] = 0.f;

    const int arow = ((lane >> 3) & 1) * 8 + (lane & 7);
    const int acol = (lane >> 4) * 8;
    const int brow = ((lane >> 4) & 1) * 8 + (lane & 7);
    const int bcol = ((lane >> 3) & 1) * 8;

#pragma unroll 1
    for (int c = 0; c < NC; c++) {
        if (c + 1 < NC) CP_WAIT(1); else CP_WAIT(0);
        __syncthreads();
        const int sel = c & 1;
        const uint32_t bA = sb + WS_A(sel);
        const uint32_t bB = sb + WS_B(sel);
#pragma unroll
        for (int ks = 0; ks < 64; ks += 16) {
            uint32_t ah[4][4];
#pragma unroll
            for (int mf = 0; mf < 4; mf++) {
                const uint32_t ao = (uint32_t)((mf * 16 + arow) * LDR + (ks + acol) * 2);
                LDSM4(ah[mf][0], ah[mf][1], ah[mf][2], ah[mf][3], bA + ao);
            }
#pragma unroll
            for (int nq = 0; nq < 4; nq++) {
                const uint32_t bo = (uint32_t)((nbase + nq * 16 + brow) * LDR
                                               + (ks + bcol) * 2);
                uint32_t b[4];
                LDSM4(b[0], b[1], b[2], b[3], bB + bo);
#pragma unroll
                for (int mf = 0; mf < 4; mf++) {
                    MMA16816(acc[mf][nq * 2],     ah[mf], b[0], b[1]);
                    MMA16816(acc[mf][nq * 2 + 1], ah[mf], b[2], b[3]);
                }
            }
        }
        __syncthreads();
        if (c + 2 < NC) load_chunk(c + 2, sel);
    }

    // ---------------- epilogue: bias -> LN stats ----------------------------
#pragma unroll
    for (int mf = 0; mf < 4; mf++)
#pragma unroll
        for (int rh = 0; rh < 2; rh++) {
            float s = 0.f, s2 = 0.f;
#pragma unroll
            for (int idx = 0; idx < 8; idx++) {
                const int c0 = nbase + idx * 8 + (lane & 3) * 2;
                float v0 = acc[mf][idx][rh * 2]     + sBias[c0];
                float v1 = acc[mf][idx][rh * 2 + 1] + sBias[c0 + 1];
                acc[mf][idx][rh * 2] = v0; acc[mf][idx][rh * 2 + 1] = v1;
                s += v0 + v1; s2 += v0 * v0 + v1 * v1;
            }
            s  += __shfl_xor_sync(0xffffffffu, s, 1);
            s  += __shfl_xor_sync(0xffffffffu, s, 2);
            s2 += __shfl_xor_sync(0xffffffffu, s2, 1);
            s2 += __shfl_xor_sync(0xffffffffu, s2, 2);
            if ((lane & 3) == 0) {
                const int row = mf * 16 + (lane >> 2) + rh * 8;
                atomicAdd(&sSum[row], s);
                atomicAdd(&sSum2[row], s2);
            }
        }
    __syncthreads();
    if (tid < 64) {
        const float mu = sSum[tid] * (1.f / 512.f);
        const float var = sSum2[tid] * (1.f / 512.f) - mu * mu;
        sMu[tid] = mu; sRs[tid] = rsqrtf(var + 1e-5f);
    }
    __syncthreads();

    // ---------------- LN + SiLU, store fp16 or fused z = tanh(h@W3+b3) ------
#pragma unroll
    for (int mf = 0; mf < 4; mf++)
#pragma unroll
        for (int rh = 0; rh < 2; rh++) {
            const int row = mf * 16 + (lane >> 2) + rh * 8;
            const float mu = sMu[row], rs = sRs[row];
            float zp[8];
            if (WRITE_Z) {
#pragma unroll
                for (int j = 0; j < 8; j++) zp[j] = 0.f;
            }
            const size_t rowg = (size_t)tile * 64 + row;
#pragma unroll
            for (int idx = 0; idx < 8; idx++) {
                const int c0 = nbase + idx * 8 + (lane & 3) * 2;
                float y0 = (acc[mf][idx][rh * 2]     - mu) * rs * sG[c0]     + sBe[c0];
                float y1 = (acc[mf][idx][rh * 2 + 1] - mu) * rs * sG[c0 + 1] + sBe[c0 + 1];
                y0 = y0 * (1.f / (1.f + __expf(-y0)));
                y1 = y1 * (1.f / (1.f + __expf(-y1)));
                if (WRITE_Z) {
                    const float* w0 = sW3 + c0 * 8;
#pragma unroll
                    for (int j = 0; j < 8; j++) {
                        zp[j] = fmaf(y0, w0[j], zp[j]);
                        zp[j] = fmaf(y1, w0[8 + j], zp[j]);
                    }
                } else {
                    *(uint32_t*)(O + rowg * 512 + c0) = pack_h2(y0, y1);
                }
            }
            if (WRITE_Z) {
#pragma unroll
                for (int j = 0; j < 8; j++) {
                    zp[j] += __shfl_xor_sync(0xffffffffu, zp[j], 1);
                    zp[j] += __shfl_xor_sync(0xffffffffu, zp[j], 2);
                }
                if ((lane & 3) == 0)
#pragma unroll
                    for (int j = 0; j < 8; j++)
                        atomicAdd(&sZ[row * 8 + j], zp[j]);
            }
        }

    if (WRITE_Z) {
        __syncthreads();
        if (tid < 64) {
            const size_t rowg = (size_t)tile * 64 + tid;
#pragma unroll
            for (int j = 0; j < 8; j++)
                z0out[rowg * 8 + j] = tanhf(sZ[tid * 8 + j] + __ldg(b3 + j));
        }
    }
}

// ============================================================================
// enc1 layer (K=64): 512 threads = 16 warps (2Mx8N), warp m32 x n64, single
// 64-K chunk (round-12 configuration: 16 warps cover the unpipelined load).
// ============================================================================
__global__ __launch_bounds__(512, 1)
void enc1_mma_kernel(const __half* __restrict__ A,
                     const __half* __restrict__ W,
                     const float* __restrict__ bias,
                     const float* __restrict__ gamma,
                     const float* __restrict__ beta,
                     __half* __restrict__ O)
{
    extern __shared__ char smem[];
    const uint32_t sb = smem_u32(smem);
    const int tid = threadIdx.x, lane = tid & 31, w = tid >> 5;
    const int warpM = w >> 3, warpN = w & 7;          // 2 x 8
    const int nbase = warpN * 64;
    const int tile = blockIdx.x;                      // 64-row tile

    float* sBias = (float*)(smem + WS_PAR);
    float* sG    = (float*)(smem + WS_PAR + 2048);
    float* sBe   = (float*)(smem + WS_PAR + 4096);
    float* sSum  = (float*)(smem + WS_RED);
    float* sSum2 = (float*)(smem + WS_RED + 256);
    float* sMu   = (float*)(smem + WS_RED + 512);
    float* sRs   = (float*)(smem + WS_RED + 768);

    sBias[tid] = bias[tid]; sG[tid] = gamma[tid]; sBe[tid] = beta[tid];
    if (tid < 64) { sSum[tid] = 0.f; sSum2[tid] = 0.f; }

    {   // single chunk load: B (512 rows x 128B), A (64 rows x 128B)
        const uint32_t bB = sb + WS_B(0);
#pragma unroll
        for (int i = tid; i < 4096; i += 512) {
            const int row = i >> 3, j = i & 7;
            cp16(bB + row * LDR + j * 16,
                 (const char*)W + ((size_t)row * 64) * 2 + j * 16);
        }
        {
            const int row = tid >> 3, j = tid & 7;
            cp16(sb + WS_A(0) + row * LDR + j * 16,
                 (const char*)A + (((size_t)tile * 64 + row) * 64) * 2 + j * 16);
        }
        CP_COMMIT();
    }

    float acc[2][8][4];
#pragma unroll
    for (int i = 0; i < 2; i++)
#pragma unroll
        for (int j = 0; j < 8; j++)
#pragma unroll
            for (int r = 0; r < 4; r++) acc[i][j][r] = 0.f;

    const int arow = ((lane >> 3) & 1) * 8 + (lane & 7);
    const int acol = (lane >> 4) * 8;
    const int brow = ((lane >> 4) & 1) * 8 + (lane & 7);
    const int bcol = ((lane >> 3) & 1) * 8;

    CP_WAIT(0);
    __syncthreads();
    {
        const uint32_t bA = sb + WS_A(0);
        const uint32_t bB = sb + WS_B(0);
#pragma unroll
        for (int ks = 0; ks < 64; ks += 16) {
            uint32_t ah[2][4];
#pragma unroll
            for (int mf = 0; mf < 2; mf++) {
                const uint32_t ao = (uint32_t)((warpM * 32 + mf * 16 + arow) * LDR
                                               + (ks + acol) * 2);
                LDSM4(ah[mf][0], ah[mf][1], ah[mf][2], ah[mf][3], bA + ao);
            }
#pragma unroll
            for (int nq = 0; nq < 4; nq++) {
                const uint32_t bo = (uint32_t)((nbase + nq * 16 + brow) * LDR
                                               + (ks + bcol) * 2);
                uint32_t b[4];
                LDSM4(b[0], b[1], b[2], b[3], bB + bo);
#pragma unroll
                for (int mf = 0; mf < 2; mf++) {
                    MMA16816(acc[mf][nq * 2],     ah[mf], b[0], b[1]);
                    MMA16816(acc[mf][nq * 2 + 1], ah[mf], b[2], b[3]);
                }
            }
        }
    }

    // epilogue: bias -> LN stats -> LN + SiLU + store
#pragma unroll
    for (int mf = 0; mf < 2; mf++)
#pragma unroll
        for (int rh = 0; rh < 2; rh++) {
            float s = 0.f, s2 = 0.f;
#pragma unroll
            for (int idx = 0; idx < 8; idx++) {
                const int c0 = nbase + idx * 8 + (lane & 3) * 2;
                float v0 = acc[mf][idx][rh * 2]     + sBias[c0];
                float v1 = acc[mf][idx][rh * 2 + 1] + sBias[c0 + 1];
                acc[mf][idx][rh * 2] = v0; acc[mf][idx][rh * 2 + 1] = v1;
                s += v0 + v1; s2 += v0 * v0 + v1 * v1;
            }
            s  += __shfl_xor_sync(0xffffffffu, s, 1);
            s  += __shfl_xor_sync(0xffffffffu, s, 2);
            s2 += __shfl_xor_sync(0xffffffffu, s2, 1);
            s2 += __shfl_xor_sync(0xffffffffu, s2, 2);
            if ((lane & 3) == 0) {
                const int row = warpM * 32 + mf * 16 + (lane >> 2) + rh * 8;
                atomicAdd(&sSum[row], s);
                atomicAdd(&sSum2[row], s2);
            }
        }
    __syncthreads();
    if (tid < 64) {
        const float mu = sSum[tid] * (1.f / 512.f);
        const float var = sSum2[tid] * (1.f / 512.f) - mu * mu;
        sMu[tid] = mu; sRs[tid] = rsqrtf(var + 1e-5f);
    }
    __syncthreads();

#pragma unroll
    for (int mf = 0; mf < 2; mf++)
#pragma unroll
        for (int rh = 0; rh < 2; rh++) {
            const int row = warpM * 32 + mf * 16 + (lane >> 2) + rh * 8;
            const float mu = sMu[row], rs = sRs[row];
            const size_t rowg = (size_t)tile * 64 + row;
#pragma unroll
            for (int idx = 0; idx < 8; idx++) {
                const int c0 = nbase + idx * 8 + (lane & 3) * 2;
                float y0 = (acc[mf][idx][rh * 2]     - mu) * rs * sG[c0]     + sBe[c0];
                float y1 = (acc[mf][idx][rh * 2 + 1] - mu) * rs * sG[c0 + 1] + sBe[c0 + 1];
                y0 = y0 * (1.f / (1.f + __expf(-y0)));
                y1 = y1 * (1.f / (1.f + __expf(-y1)));
                *(uint32_t*)(O + rowg * 512 + c0) = pack_h2(y0, y1);
            }
        }
}

// ============================================================================
// out layer: out[B,64] = A[B,512] @ W3 + b3 (fp32 out, no LN).
// CTA: M=128, N=64. 256 thr = 8 warps (4Mx2N), warp m32 x n32. BK=64,
// 2-stage, 2 CTAs/SM. (Unchanged.)
// ============================================================================
#define OST      27648
#define OS_A(s)  ((s) * OST)                    // 128*144 = 18432
#define OS_B(s)  ((s) * OST + 18432)            // 64*144  = 9216
#define SM_OUT   55296

__global__ __launch_bounds__(256, 2)
void out_mma_kernel(const __half* __restrict__ A,
                    const __half* __restrict__ W,
                    const float* __restrict__ bias,
                    float* __restrict__ out)
{
    constexpr int NC = 8;
    extern __shared__ char smem[];
    const uint32_t sb = smem_u32(smem);
    const int tid = threadIdx.x, lane = tid & 31, w = tid >> 5;
    const int warpM = w >> 1, warpN = w & 1;
    const int nbase = warpN * 32;
    const int tile = blockIdx.x;

    auto load_chunk = [&](int c, int sel) {
        const int kbase = c * 64;
#pragma unroll
        for (int i = tid; i < 512; i += 256) {       // 64 rows x 8 quads
            const int row = i >> 3, j = i & 7;
            cp16(sb + OS_B(sel) + row * LDR + j * 16,
                 (const char*)W + ((size_t)row * 512 + kbase) * 2 + j * 16);
        }
#pragma unroll
        for (int i = tid; i < 1024; i += 256) {      // 128 rows x 8 quads
            const int row = i >> 3, j = i & 7;
            cp16(sb + OS_A(sel) + row * LDR + j * 16,
                 (const char*)A + (((size_t)tile * 128 + row) * 512 + kbase) * 2 + j * 16);
        }
        CP_COMMIT();
    };

    load_chunk(0, 0);
    load_chunk(1, 1);

    float acc[2][4][4];
#pragma unroll
    for (int i = 0; i < 2; i++)
#pragma unroll
        for (int j = 0; j < 4; j++)
#pragma unroll
            for (int r = 0; r < 4; r++) acc[i][j][r] = 0.f;

    const int arow = ((lane >> 3) & 1) * 8 + (lane & 7);
    const int acol = (lane >> 4) * 8;
    const int brow = ((lane >> 4) & 1) * 8 + (lane & 7);
    const int bcol = ((lane >> 3) & 1) * 8;

#pragma unroll 1
    for (int c = 0; c < NC; c++) {
        if (c + 1 < NC) CP_WAIT(1); else CP_WAIT(0);
        __syncthreads();
        const int sel = c & 1;
        const uint32_t bA = sb + OS_A(sel);
        const uint32_t bB = sb + OS_B(sel);
#pragma unroll
        for (int ks = 0; ks < 64; ks += 16) {
            uint32_t ah[2][4];
#pragma unroll
            for (int mf = 0; mf < 2; mf++) {
                const uint32_t ao = (uint32_t)((warpM * 32 + mf * 16 + arow) * LDR
                                               + (ks + acol) * 2);
                LDSM4(ah[mf][0], ah[mf][1], ah[mf][2], ah[mf][3], bA + ao);
            }
#pragma unroll
            for (int nq = 0; nq < 2; nq++) {
                const uint32_t bo = (uint32_t)((nbase + nq * 16 + brow) * LDR
                                               + (ks + bcol) * 2);
                uint32_t b[4];
                LDSM4(b[0], b[1], b[2], b[3], bB + bo);
#pragma unroll
                for (int mf = 0; mf < 2; mf++) {
                    MMA16816(acc[mf][nq * 2],     ah[mf], b[0], b[1]);
                    MMA16816(acc[mf][nq * 2 + 1], ah[mf], b[2], b[3]);
                }
            }
        }
        __syncthreads();
        if (c + 2 < NC) load_chunk(c + 2, sel);
    }

#pragma unroll
    for (int mf = 0; mf < 2; mf++)
#pragma unroll
        for (int rh = 0; rh < 2; rh++) {
            const int row = warpM * 32 + mf * 16 + (lane >> 2) + rh * 8;
            const size_t rowg = (size_t)tile * 128 + row;
#pragma unroll
            for (int idx = 0; idx < 4; idx++) {
                const int c0 = nbase + idx * 8 + (lane & 3) * 2;
                float2 o;
                o.x = acc[mf][idx][rh * 2]     + __ldg(bias + c0);
                o.y = acc[mf][idx][rh * 2 + 1] + __ldg(bias + c0 + 1);
                *(float2*)(out + rowg * 64 + c0) = o;
            }
        }
}

// ============================================================================
// integrator + FUSED dec layer 1. launch_bounds(256,2) -> 128 regs (no
// spills; (256,4) capped phase 2 at 64 regs and spilled). Phase-2 columns
// mapped c0 = j*64 + lane*2 so outputs store as packed half2 (coalesced).
// ============================================================================
__global__ __launch_bounds__(256, 2)
void integrate_dec1_kernel(const float* __restrict__ z0,
                           const float* __restrict__ dtv,
                           const float* __restrict__ Xi,
                           const float* __restrict__ W1,   // dec_W1 [8][512] fp32
                           const float* __restrict__ b1,
                           const float* __restrict__ g1,
                           const float* __restrict__ be1,
                           __half* __restrict__ O)
{
    __shared__ float Xis[NTH * LDIM];
    __shared__ float sW[8 * 512];
    __shared__ float sB1[512], sG1[512], sBe1[512];
    __shared__ float sZr[256 * 9];                 // padded row stride 9

    const int tid = threadIdx.x, lane = tid & 31, w = tid >> 5;
    for (int i = tid; i < NTH * LDIM; i += 256) Xis[i] = Xi[i];
    for (int i = tid; i < 8 * 512; i += 256) sW[i] = W1[i];
    for (int i = tid; i < 512; i += 256) { sB1[i] = b1[i]; sG1[i] = g1[i]; sBe1[i] = be1[i]; }
    __syncthreads();

    // ---- phase 1: per-thread latent integration ----
    const size_t row = (size_t)blockIdx.x * 256 + tid;
    float z[8];
    *(float4*)&z[0] = *(const float4*)(z0 + row * 8);
    *(float4*)&z[4] = *(const float4*)(z0 + row * 8 + 4);
    const float dt = dtv[row] * (1.f / (float)NSTEPS);

#pragma unroll 1
    for (int s = 0; s < NSTEPS; s++) {
        float zd[8];
#pragma unroll
        for (int j = 0; j < 8; j++) zd[j] = Xis[j];
#pragma unroll
        for (int i = 0; i < 8; i++) {
            const float t = z[i];
#pragma unroll
            for (int j = 0; j < 8; j++)
                zd[j] = fmaf(t, Xis[(1 + i) * 8 + j], zd[j]);
        }
        int idx = 9;
#pragma unroll
        for (int i = 0; i < 8; i++)
#pragma unroll
            for (int k = i; k < 8; k++) {
                const float q = z[i] * z[k];
#pragma unroll
                for (int j = 0; j < 8; j++)
                    zd[j] = fmaf(q, Xis[idx * 8 + j], zd[j]);
                idx++;
            }
#pragma unroll
        for (int j = 0; j < 8; j++) z[j] = fmaf(zd[j], dt, z[j]);
    }
#pragma unroll
    for (int j = 0; j < 8; j++) sZr[tid * 9 + j] = z[j];
    __syncthreads();

    // ---- phase 2: warp-per-row dec1 matvec + LN + SiLU (vectorized store) --
    const size_t rowbase = (size_t)blockIdx.x * 256;
#pragma unroll 1
    for (int it = 0; it < 32; it++) {
        const int lr = it * 8 + w;                 // local row 0..255
        float zz[8];
#pragma unroll
        for (int k = 0; k < 8; k++) zz[k] = sZr[lr * 9 + k];   // broadcast
        float a0[8], a1[8];
#pragma unroll
        for (int j = 0; j < 8; j++) {
            const int c0 = j * 64 + lane * 2;
            float x0 = sB1[c0], x1 = sB1[c0 + 1];
#pragma unroll
            for (int k = 0; k < 8; k++) {
                x0 = fmaf(zz[k], sW[k * 512 + c0],     x0);
                x1 = fmaf(zz[k], sW[k * 512 + c0 + 1], x1);
            }
            a0[j] = x0; a1[j] = x1;
        }
        float s = 0.f, s2 = 0.f;
#pragma unroll
        for (int j = 0; j < 8; j++) {
            s += a0[j] + a1[j]; s2 += a0[j] * a0[j] + a1[j] * a1[j];
        }
#pragma unroll
        for (int o = 16; o; o >>= 1) {
            s  += __shfl_xor_sync(0xffffffffu, s, o);
            s2 += __shfl_xor_sync(0xffffffffu, s2, o);
        }
        const float mu = s * (1.f / 512.f);
        const float rs = rsqrtf(s2 * (1.f / 512.f) - mu * mu + 1e-5f);
        __half* orow = O + (rowbase + lr) * 512;
#pragma unroll
        for (int j = 0; j < 8; j++) {
            const int c0 = j * 64 + lane * 2;
            float y0 = (a0[j] - mu) * rs * sG1[c0]     + sBe1[c0];
            float y1 = (a1[j] - mu) * rs * sG1[c0 + 1] + sBe1[c0 + 1];
            y0 = y0 * (1.f / (1.f + __expf(-y0)));
            y1 = y1 * (1.f / (1.f + __expf(-y1)));
            *(uint32_t*)(orow + c0) = pack_h2(y0, y1);
        }
    }
}

// ============================================================================
extern "C" void kernel_launch(void* const* d_in, const int* in_sizes, int n_in,
                              void* d_out, int out_size)
{
    (void)in_sizes; (void)n_in; (void)out_size;
    const float* x0   = (const float*)d_in[0];
    const float* dtn  = (const float*)d_in[1];
    const float* eW1  = (const float*)d_in[4];
    const float* eb1  = (const float*)d_in[5];
    const float* eg1  = (const float*)d_in[6];
    const float* ebe1 = (const float*)d_in[7];
    const float* eW2  = (const float*)d_in[8];
    const float* eb2  = (const float*)d_in[9];
    const float* eg2  = (const float*)d_in[10];
    const float* ebe2 = (const float*)d_in[11];
    const float* eW3  = (const float*)d_in[12];
    const float* eb3  = (const float*)d_in[13];
    const float* dW1  = (const float*)d_in[14];
    const float* db1  = (const float*)d_in[15];
    const float* dg1  = (const float*)d_in[16];
    const float* dbe1 = (const float*)d_in[17];
    const float* dW2  = (const float*)d_in[18];
    const float* db2  = (const float*)d_in[19];
    const float* dg2  = (const float*)d_in[20];
    const float* dbe2 = (const float*)d_in[21];
    const float* dW3  = (const float*)d_in[22];
    const float* db3  = (const float*)d_in[23];
    const float* Xi   = (const float*)d_in[24];
    float* out = (float*)d_out;

    __half *hA, *hB, *xh;
    __half *w1, *w2, *d2, *d3;
    float* z0;
    cudaGetSymbolAddress((void**)&hA, g_hA);
    cudaGetSymbolAddress((void**)&hB, g_hB);
    cudaGetSymbolAddress((void**)&xh, g_x);
    cudaGetSymbolAddress((void**)&z0, g_z0);
    cudaGetSymbolAddress((void**)&w1, g_w1);
    cudaGetSymbolAddress((void**)&w2, g_w2);
    cudaGetSymbolAddress((void**)&d2, g_d2);
    cudaGetSymbolAddress((void**)&d3, g_d3);

    cudaFuncSetAttribute(enc1_mma_kernel,
        cudaFuncAttributeMaxDynamicSharedMemorySize, SM_WIDE);
    cudaFuncSetAttribute(wide_mma_k512<false>,
        cudaFuncAttributeMaxDynamicSharedMemorySize, SM_WIDE);
    cudaFuncSetAttribute(wide_mma_k512<true>,
        cudaFuncAttributeMaxDynamicSharedMemorySize, SM_WIDE);
    cudaFuncSetAttribute(out_mma_kernel,
        cudaFuncAttributeMaxDynamicSharedMemorySize, SM_OUT);

    // ---- prep ----
    prep_all_kernel<<<(SEG3 + 255) / 256, 256>>>(eW1, eW2, dW2, dW3,
                                                 w1, w2, d2, d3);
    prep_x_kernel<<<(BATCH * 64) / 256, 256>>>(x0, xh);

    const int nwide = BATCH / 64;    // 2048

    // ---- pipeline ----
    // encoder layer 1 (K=64, 512-thread variant)
    enc1_mma_kernel<<<nwide, 512, SM_WIDE>>>(xh, w1, eb1, eg1, ebe1, hA);
    // encoder layer 2 + fused layer 3 -> z0 (256-thread m64n64 variant)
    wide_mma_k512<true><<<nwide, 256, SM_WIDE>>>(
        hA, w2, eb2, eg2, ebe2, nullptr, eW3, eb3, z0);
    // integrator + fused decoder layer 1 -> hA
    integrate_dec1_kernel<<<BATCH / 256, 256>>>(z0, dtn, Xi, dW1, db1, dg1, dbe1, hA);
    // decoder layer 2
    wide_mma_k512<false><<<nwide, 256, SM_WIDE>>>(
        hA, d2, db2, dg2, dbe2, hB, nullptr, nullptr, nullptr);
    // decoder output layer
    out_mma_kernel<<<BATCH / 128, 256, SM_OUT>>>(hB, d3, db3, out);
}